// round 2
// baseline (speedup 1.0000x reference)
#include <cuda_runtime.h>
#include <math.h>

typedef unsigned long long u64;

// ---- problem constants ----
#define B_    64
#define CIN   16
#define H_    256
#define W_    256
#define COUT  64
#define OH    254
#define OW    254

// ---- tiling ----
#define TILE      32        // 32x32 output pixels per CTA
#define THREADS   256       // 16x16 threads, 2x2 quad each
#define XT        34        // input halo tile edge
#define XPITCH    36        // padded row stride (floats)

#define SMEM_X_FLOATS  (CIN * XT * XPITCH)        // 19584
#define SMEM_W_FLOATS  (CIN * 9 * COUT)           // 9216
#define SMEM_FLOATS    (SMEM_X_FLOATS + SMEM_W_FLOATS + COUT)
#define SMEM_BYTES     (SMEM_FLOATS * 4)          // 115456

// ---- f32x2 packed helpers (sm_100+ only; ptxas never auto-fuses) ----
__device__ __forceinline__ u64 pk2(float v) {
    u64 r; asm("mov.b64 %0, {%1, %1};" : "=l"(r) : "f"(v)); return r;
}
__device__ __forceinline__ u64 ffma2(u64 a, u64 b, u64 c) {
    u64 d; asm("fma.rn.f32x2 %0, %1, %2, %3;" : "=l"(d) : "l"(a), "l"(b), "l"(c)); return d;
}
__device__ __forceinline__ void upk(u64 v, float& lo, float& hi) {
    asm("mov.b64 {%0, %1}, %2;" : "=f"(lo), "=f"(hi) : "l"(v));
}

__global__ __launch_bounds__(THREADS, 1)
void conv_min_tanh_kernel(const float* __restrict__ x,
                          const float* __restrict__ wg,
                          const float* __restrict__ bias,
                          float* __restrict__ out)
{
    extern __shared__ float smem[];
    float* sx = smem;                    // [CIN][XT][XPITCH]
    float* sw = smem + SMEM_X_FLOATS;    // [ci][kh][kw][co]
    float* sb = sw + SMEM_W_FLOATS;      // [COUT]

    const int tid  = threadIdx.x;
    const int b    = blockIdx.z;
    const int row0 = blockIdx.y * TILE;
    const int col0 = blockIdx.x * TILE;

    // ---- load input halo tile (zero-fill OOB) ----
    {
        const int total = CIN * XT * XT;   // 18496
        const float* xb = x + (size_t)b * CIN * H_ * W_;
        #pragma unroll 1
        for (int i = tid; i < total; i += THREADS) {
            int ci  = i / (XT * XT);
            int rem = i - ci * (XT * XT);
            int r   = rem / XT;
            int c   = rem - r * XT;
            int gr = row0 + r, gc = col0 + c;
            float v = 0.0f;
            if (gr < H_ && gc < W_)
                v = xb[ci * (H_ * W_) + gr * W_ + gc];
            sx[(ci * XT + r) * XPITCH + c] = v;
        }
    }
    // ---- load weights, transposed to [ci][kh][kw][co] ----
    {
        #pragma unroll 1
        for (int i = tid; i < SMEM_W_FLOATS; i += THREADS) {
            int co   = i & 63;
            int rest = i >> 6;           // (ci*3+kh)*3+kw
            int kw   = rest % 3;
            int r2   = rest / 3;
            int kh   = r2 % 3;
            int ci   = r2 / 3;
            sw[i] = wg[((co * CIN + ci) * 3 + kh) * 3 + kw];
        }
        if (tid < COUT) sb[tid] = bias[tid];
    }
    __syncthreads();

    // ---- compute: 2x2 quad per thread, co packed in pairs (f32x2) ----
    const int tx = tid & 15;
    const int ty = tid >> 4;
    const int lr = 2 * ty;     // quad origin in tile (row)
    const int lc = 2 * tx;     // quad origin in tile (col)

    float m0 = INFINITY, m1 = INFINITY, m2 = INFINITY, m3 = INFINITY;

    #pragma unroll 1
    for (int cb = 0; cb < COUT / 8; cb++) {
        // init accumulators with bias pairs (co = cb*8 + 2j, +1)
        const u64* bp = (const u64*)(sb + cb * 8);
        u64 acc0[4], acc1[4], acc2[4], acc3[4];
        #pragma unroll
        for (int j = 0; j < 4; j++) {
            u64 bj = bp[j];
            acc0[j] = bj; acc1[j] = bj; acc2[j] = bj; acc3[j] = bj;
        }

        #pragma unroll 1
        for (int ci = 0; ci < CIN; ci++) {
            // 4x4 x-window, dup-packed
            const float* xb = sx + (ci * XT + lr) * XPITCH + lc;
            u64 xd[4][4];
            #pragma unroll
            for (int r = 0; r < 4; r++) {
                float2 a  = *(const float2*)(xb + r * XPITCH);
                float2 b2 = *(const float2*)(xb + r * XPITCH + 2);
                xd[r][0] = pk2(a.x);  xd[r][1] = pk2(a.y);
                xd[r][2] = pk2(b2.x); xd[r][3] = pk2(b2.y);
            }
            const float* wbase = sw + (ci * 9) * COUT + cb * 8;
            #pragma unroll
            for (int kh = 0; kh < 3; kh++) {
                #pragma unroll
                for (int kw = 0; kw < 3; kw++) {
                    // 8 weights (4 co-pairs), warp-uniform broadcast LDS
                    const ulonglong2* wp = (const ulonglong2*)(wbase + (kh * 3 + kw) * COUT);
                    ulonglong2 wA = wp[0];
                    ulonglong2 wB = wp[1];
                    u64 w0 = wA.x, w1 = wA.y, w2 = wB.x, w3 = wB.y;
                    u64 xa = xd[kh][kw];
                    u64 xbv = xd[kh][kw + 1];
                    u64 xc = xd[kh + 1][kw];
                    u64 xdv = xd[kh + 1][kw + 1];
                    acc0[0] = ffma2(xa,  w0, acc0[0]);
                    acc0[1] = ffma2(xa,  w1, acc0[1]);
                    acc0[2] = ffma2(xa,  w2, acc0[2]);
                    acc0[3] = ffma2(xa,  w3, acc0[3]);
                    acc1[0] = ffma2(xbv, w0, acc1[0]);
                    acc1[1] = ffma2(xbv, w1, acc1[1]);
                    acc1[2] = ffma2(xbv, w2, acc1[2]);
                    acc1[3] = ffma2(xbv, w3, acc1[3]);
                    acc2[0] = ffma2(xc,  w0, acc2[0]);
                    acc2[1] = ffma2(xc,  w1, acc2[1]);
                    acc2[2] = ffma2(xc,  w2, acc2[2]);
                    acc2[3] = ffma2(xc,  w3, acc2[3]);
                    acc3[0] = ffma2(xdv, w0, acc3[0]);
                    acc3[1] = ffma2(xdv, w1, acc3[1]);
                    acc3[2] = ffma2(xdv, w2, acc3[2]);
                    acc3[3] = ffma2(xdv, w3, acc3[3]);
                }
            }
        }
        // min-reduce this co-block
        #pragma unroll
        for (int j = 0; j < 4; j++) {
            float lo, hi;
            upk(acc0[j], lo, hi); m0 = fminf(m0, fminf(lo, hi));
            upk(acc1[j], lo, hi); m1 = fminf(m1, fminf(lo, hi));
            upk(acc2[j], lo, hi); m2 = fminf(m2, fminf(lo, hi));
            upk(acc3[j], lo, hi); m3 = fminf(m3, fminf(lo, hi));
        }
    }

    // ---- tanh(tanh(min)) and store ----
    float* ob = out + (size_t)b * OH * OW;
    int orow = row0 + lr, ocol = col0 + lc;
    if (orow < OH) {
        if (ocol < OW)     ob[orow * OW + ocol]     = tanhf(tanhf(m0));
        if (ocol + 1 < OW) ob[orow * OW + ocol + 1] = tanhf(tanhf(m1));
    }
    if (orow + 1 < OH) {
        if (ocol < OW)     ob[(orow + 1) * OW + ocol]     = tanhf(tanhf(m2));
        if (ocol + 1 < OW) ob[(orow + 1) * OW + ocol + 1] = tanhf(tanhf(m3));
    }
}

extern "C" void kernel_launch(void* const* d_in, const int* in_sizes, int n_in,
                              void* d_out, int out_size)
{
    const float* x    = (const float*)d_in[0];
    const float* wg   = (const float*)d_in[1];
    const float* bias = (const float*)d_in[2];
    float* out = (float*)d_out;

    cudaFuncSetAttribute(conv_min_tanh_kernel,
                         cudaFuncAttributeMaxDynamicSharedMemorySize, SMEM_BYTES);

    dim3 grid((OW + TILE - 1) / TILE, (OH + TILE - 1) / TILE, B_);   // 8 x 8 x 64
    conv_min_tanh_kernel<<<grid, THREADS, SMEM_BYTES>>>(x, wg, bias, out);
}

// round 5
// speedup vs baseline: 1.0073x; 1.0073x over previous
#include <cuda_runtime.h>
#include <math.h>

typedef unsigned long long u64;

// ---- problem constants ----
#define B_    64
#define CIN   16
#define H_    256
#define W_    256
#define COUT  64
#define OH    254
#define OW    254

// ---- tiling: 32(h) x 64(w) outputs per CTA, 512 threads, 2x2 quad/thread ----
#define TILE_H    32
#define TILE_W    64
#define THREADS   512
#define XT_H      34        // halo rows
#define XT_W      66        // halo cols
#define XPITCH    68        // padded row stride (floats)

#define SMEM_X_FLOATS  (CIN * XT_H * XPITCH)      // 36992
#define SMEM_W_FLOATS  (CIN * 9 * COUT)           // 9216
#define SMEM_FLOATS    (SMEM_X_FLOATS + SMEM_W_FLOATS + COUT)
#define SMEM_BYTES     (SMEM_FLOATS * 4)          // 185088

// ---- f32x2 packed helpers (sm_100+; ptxas never auto-fuses) ----
__device__ __forceinline__ u64 pk2(float v) {
    u64 r; asm("mov.b64 %0, {%1, %1};" : "=l"(r) : "f"(v)); return r;
}
__device__ __forceinline__ u64 ffma2(u64 a, u64 b, u64 c) {
    u64 d; asm("fma.rn.f32x2 %0, %1, %2, %3;" : "=l"(d) : "l"(a), "l"(b), "l"(c)); return d;
}
__device__ __forceinline__ void upk(u64 v, float& lo, float& hi) {
    asm("mov.b64 {%0, %1}, %2;" : "=f"(lo), "=f"(hi) : "l"(v));
}

__global__ __launch_bounds__(THREADS, 1)
void conv_min_tanh_kernel(const float* __restrict__ x,
                          const float* __restrict__ wg,
                          const float* __restrict__ bias,
                          float* __restrict__ out)
{
    extern __shared__ float smem[];
    float* sx = smem;                    // [CIN][XT_H][XPITCH]
    float* sw = smem + SMEM_X_FLOATS;    // [ci][kh][kw][co]
    float* sb = sw + SMEM_W_FLOATS;      // [COUT]

    const int tid  = threadIdx.x;
    const int b    = blockIdx.z;
    const int row0 = blockIdx.y * TILE_H;
    const int col0 = blockIdx.x * TILE_W;

    // ---- load input halo tile (zero-fill OOB) ----
    {
        const int total = CIN * XT_H * XT_W;   // 35904
        const float* xb = x + (size_t)b * CIN * H_ * W_;
        #pragma unroll 1
        for (int i = tid; i < total; i += THREADS) {
            int ci  = i / (XT_H * XT_W);
            int rem = i - ci * (XT_H * XT_W);
            int r   = rem / XT_W;
            int c   = rem - r * XT_W;
            int gr = row0 + r, gc = col0 + c;
            float v = 0.0f;
            if (gr < H_ && gc < W_)
                v = xb[ci * (H_ * W_) + gr * W_ + gc];
            sx[(ci * XT_H + r) * XPITCH + c] = v;
        }
    }
    // ---- load weights, transposed to [ci][kh][kw][co] ----
    {
        #pragma unroll 1
        for (int i = tid; i < SMEM_W_FLOATS; i += THREADS) {
            int co   = i & 63;
            int rest = i >> 6;           // (ci*3+kh)*3+kw
            int kw   = rest % 3;
            int r2   = rest / 3;
            int kh   = r2 % 3;
            int ci   = r2 / 3;
            sw[i] = wg[((co * CIN + ci) * 3 + kh) * 3 + kw];
        }
        if (tid < COUT) sb[tid] = bias[tid];
    }
    __syncthreads();

    // ---- compute: 2x2 quad per thread, co packed in pairs (f32x2) ----
    const int tx = tid & 31;     // 32 cols of threads
    const int ty = tid >> 5;     // 16 rows of threads
    const int lr = 2 * ty;       // quad origin in tile (row)
    const int lc = 2 * tx;       // quad origin in tile (col)

    float m0 = INFINITY, m1 = INFINITY, m2 = INFINITY, m3 = INFINITY;

    #pragma unroll 1
    for (int cb = 0; cb < COUT / 8; cb++) {
        const u64* bp = (const u64*)(sb + cb * 8);
        u64 acc0[4], acc1[4], acc2[4], acc3[4];
        #pragma unroll
        for (int j = 0; j < 4; j++) {
            u64 bj = bp[j];
            acc0[j] = bj; acc1[j] = bj; acc2[j] = bj; acc3[j] = bj;
        }

        #pragma unroll 1
        for (int ci = 0; ci < CIN; ci++) {
            // 4x4 x-window, dup-packed
            const float* xb = sx + (ci * XT_H + lr) * XPITCH + lc;
            u64 xd[4][4];
            #pragma unroll
            for (int r = 0; r < 4; r++) {
                float2 a  = *(const float2*)(xb + r * XPITCH);
                float2 b2 = *(const float2*)(xb + r * XPITCH + 2);
                xd[r][0] = pk2(a.x);  xd[r][1] = pk2(a.y);
                xd[r][2] = pk2(b2.x); xd[r][3] = pk2(b2.y);
            }
            const float* wbase = sw + (ci * 9) * COUT + cb * 8;
            #pragma unroll
            for (int kh = 0; kh < 3; kh++) {
                #pragma unroll
                for (int kw = 0; kw < 3; kw++) {
                    // 8 weights (4 co-pairs), warp-uniform broadcast LDS
                    const ulonglong2* wp = (const ulonglong2*)(wbase + (kh * 3 + kw) * COUT);
                    ulonglong2 wA = wp[0];
                    ulonglong2 wB = wp[1];
                    u64 w0 = wA.x, w1 = wA.y, w2 = wB.x, w3 = wB.y;
                    u64 xa  = xd[kh][kw];
                    u64 xbv = xd[kh][kw + 1];
                    u64 xc  = xd[kh + 1][kw];
                    u64 xdv = xd[kh + 1][kw + 1];
                    acc0[0] = ffma2(xa,  w0, acc0[0]);
                    acc0[1] = ffma2(xa,  w1, acc0[1]);
                    acc0[2] = ffma2(xa,  w2, acc0[2]);
                    acc0[3] = ffma2(xa,  w3, acc0[3]);
                    acc1[0] = ffma2(xbv, w0, acc1[0]);
                    acc1[1] = ffma2(xbv, w1, acc1[1]);
                    acc1[2] = ffma2(xbv, w2, acc1[2]);
                    acc1[3] = ffma2(xbv, w3, acc1[3]);
                    acc2[0] = ffma2(xc,  w0, acc2[0]);
                    acc2[1] = ffma2(xc,  w1, acc2[1]);
                    acc2[2] = ffma2(xc,  w2, acc2[2]);
                    acc2[3] = ffma2(xc,  w3, acc2[3]);
                    acc3[0] = ffma2(xdv, w0, acc3[0]);
                    acc3[1] = ffma2(xdv, w1, acc3[1]);
                    acc3[2] = ffma2(xdv, w2, acc3[2]);
                    acc3[3] = ffma2(xdv, w3, acc3[3]);
                }
            }
        }
        // min-reduce this co-block
        #pragma unroll
        for (int j = 0; j < 4; j++) {
            float lo, hi;
            upk(acc0[j], lo, hi); m0 = fminf(m0, fminf(lo, hi));
            upk(acc1[j], lo, hi); m1 = fminf(m1, fminf(lo, hi));
            upk(acc2[j], lo, hi); m2 = fminf(m2, fminf(lo, hi));
            upk(acc3[j], lo, hi); m3 = fminf(m3, fminf(lo, hi));
        }
    }

    // ---- tanh(tanh(min)) and store ----
    float* ob = out + (size_t)b * OH * OW;
    int orow = row0 + lr, ocol = col0 + lc;
    if (orow < OH) {
        if (ocol < OW)     ob[orow * OW + ocol]     = tanhf(tanhf(m0));
        if (ocol + 1 < OW) ob[orow * OW + ocol + 1] = tanhf(tanhf(m1));
    }
    if (orow + 1 < OH) {
        if (ocol < OW)     ob[(orow + 1) * OW + ocol]     = tanhf(tanhf(m2));
        if (ocol + 1 < OW) ob[(orow + 1) * OW + ocol + 1] = tanhf(tanhf(m3));
    }
}

extern "C" void kernel_launch(void* const* d_in, const int* in_sizes, int n_in,
                              void* d_out, int out_size)
{
    const float* x    = (const float*)d_in[0];
    const float* wg   = (const float*)d_in[1];
    const float* bias = (const float*)d_in[2];
    float* out = (float*)d_out;

    cudaFuncSetAttribute(conv_min_tanh_kernel,
                         cudaFuncAttributeMaxDynamicSharedMemorySize, SMEM_BYTES);

    dim3 grid((OW + TILE_W - 1) / TILE_W, (OH + TILE_H - 1) / TILE_H, B_);  // 4 x 8 x 64
    conv_min_tanh_kernel<<<grid, THREADS, SMEM_BYTES>>>(x, wg, bias, out);
}